// round 4
// baseline (speedup 1.0000x reference)
#include <cuda_runtime.h>

#define BATCH   32
#define NP      4096
#define THREADS 128
#define QPT     2                      // queries per thread
#define QBLK    (THREADS * QPT)        // 256 queries per block
#define BLKX    (NP / QBLK)            // 16 blocks per (batch, direction)
#define TILE    2048                   // candidates per smem tile (32 KB)

// Preprocessed candidates, pair-transposed for f32x2:
//   pair p -> entry 2p   = (x_{2p}, x_{2p+1}, y_{2p}, y_{2p+1})   as ulonglong2
//             entry 2p+1 = (z_{2p}, z_{2p+1}, cc_{2p}, cc_{2p+1}) as ulonglong2
// where x,y,z already scaled by -2 and cc = ||c||^2.
// One ulonglong2 (16 B) per candidate on average.
__device__ ulonglong2 g_pre2[2 * BATCH * NP];
__device__ float      g_part[2][BATCH][BLKX];

static __device__ __forceinline__ unsigned long long fma2(
    unsigned long long a, unsigned long long b, unsigned long long c) {
    unsigned long long d;
    asm("fma.rn.f32x2 %0, %1, %2, %3;" : "=l"(d) : "l"(a), "l"(b), "l"(c));
    return d;
}
static __device__ __forceinline__ unsigned long long pack2(float x) {
    unsigned long long r;
    asm("mov.b64 %0, {%1, %1};" : "=l"(r) : "f"(x));
    return r;
}
static __device__ __forceinline__ void unpack2(unsigned long long v,
                                               float& lo, float& hi) {
    asm("mov.b64 {%0, %1}, %2;" : "=f"(lo), "=f"(hi) : "l"(v));
}
static __device__ __forceinline__ unsigned long long pk(float a, float b) {
    return ((unsigned long long)__float_as_uint(b) << 32) | __float_as_uint(a);
}

// ---------------------------------------------------------------------------
// Preprocess: one thread per candidate PAIR. raw (x,y,z) -> packed transposed.
// ---------------------------------------------------------------------------
__global__ void chamfer_pre_kernel(const float* __restrict__ x1,
                                   const float* __restrict__ x2) {
    const int pairs_per = NP / 2;
    int gid = blockIdx.x * blockDim.x + threadIdx.x;
    if (gid >= 2 * BATCH * pairs_per) return;
    int w = gid / (BATCH * pairs_per);
    int r = gid - w * (BATCH * pairs_per);
    int b = r / pairs_per;
    int p = r - b * pairs_per;

    const float* src = (w ? x2 : x1) + ((size_t)b * NP + 2 * p) * 3;
    float x0 = src[0], y0 = src[1], z0 = src[2];
    float x1v = src[3], y1v = src[4], z1v = src[5];
    float c0 = x0 * x0 + y0 * y0 + z0 * z0;
    float c1 = x1v * x1v + y1v * y1v + z1v * z1v;

    size_t base = ((size_t)w * BATCH + b) * NP + 2 * (size_t)p;
    ulonglong2 e0, e1;
    e0.x = pk(-2.0f * x0, -2.0f * x1v);
    e0.y = pk(-2.0f * y0, -2.0f * y1v);
    e1.x = pk(-2.0f * z0, -2.0f * z1v);
    e1.y = pk(c0, c1);
    g_pre2[base + 0] = e0;
    g_pre2[base + 1] = e1;
}

// ---------------------------------------------------------------------------
// Main kernel. Each thread: 2 queries vs all NP candidates (2 per iteration
// via f32x2). Per iter: 2 LDS.128 + 6 FFMA2 + 4 FMNMX.
// ---------------------------------------------------------------------------
__global__ void __launch_bounds__(THREADS)
chamfer_min_kernel(const float* __restrict__ x1, const float* __restrict__ x2) {
    __shared__ ulonglong2 sc[TILE];
    __shared__ float red[THREADS / 32];

    const int dir = blockIdx.z;
    const int b   = blockIdx.y;
    const float* qsrc = dir ? x2 : x1;
    const ulonglong2* cand = g_pre2 + ((size_t)(dir ^ 1) * BATCH + b) * NP;

    const int q0i = blockIdx.x * QBLK + threadIdx.x;
    const int q1i = q0i + THREADS;
    const float* qp0 = qsrc + ((size_t)b * NP + q0i) * 3;
    const float* qp1 = qsrc + ((size_t)b * NP + q1i) * 3;
    float qx0 = qp0[0], qy0 = qp0[1], qz0 = qp0[2];
    float qx1 = qp1[0], qy1 = qp1[1], qz1 = qp1[2];
    float qq0 = qx0 * qx0 + qy0 * qy0 + qz0 * qz0;
    float qq1 = qx1 * qx1 + qy1 * qy1 + qz1 * qz1;

    const unsigned long long Qx0 = pack2(qx0), Qy0 = pack2(qy0), Qz0 = pack2(qz0);
    const unsigned long long Qx1 = pack2(qx1), Qy1 = pack2(qy1), Qz1 = pack2(qz1);

    const float INF = __int_as_float(0x7f800000);
    float m0a = INF, m0b = INF, m1a = INF, m1b = INF;

    for (int t = 0; t < NP; t += TILE) {
        __syncthreads();
        #pragma unroll
        for (int j = threadIdx.x; j < TILE; j += THREADS)
            sc[j] = cand[t + j];
        __syncthreads();

        #pragma unroll 4
        for (int jp = 0; jp < TILE / 2; jp++) {
            ulonglong2 t0 = sc[2 * jp + 0];     // (cx2, cy2)
            ulonglong2 t1 = sc[2 * jp + 1];     // (cz2, cc2)
            unsigned long long v0 = fma2(Qx0, t0.x,
                                    fma2(Qy0, t0.y,
                                    fma2(Qz0, t1.x, t1.y)));
            unsigned long long v1 = fma2(Qx1, t0.x,
                                    fma2(Qy1, t0.y,
                                    fma2(Qz1, t1.x, t1.y)));
            float a, c;
            unpack2(v0, a, c);
            m0a = fminf(m0a, a);
            m0b = fminf(m0b, c);
            unpack2(v1, a, c);
            m1a = fminf(m1a, a);
            m1b = fminf(m1b, c);
        }
    }

    float d0 = qq0 + fminf(m0a, m0b);
    float d1 = qq1 + fminf(m1a, m1b);
    float mv = d0 + d1;

    #pragma unroll
    for (int o = 16; o > 0; o >>= 1)
        mv += __shfl_xor_sync(0xffffffffu, mv, o);
    if ((threadIdx.x & 31) == 0)
        red[threadIdx.x >> 5] = mv;
    __syncthreads();
    if (threadIdx.x == 0) {
        float s = 0.0f;
        #pragma unroll
        for (int w = 0; w < THREADS / 32; w++) s += red[w];
        g_part[dir][b][blockIdx.x] = s;
    }
}

// ---------------------------------------------------------------------------
// Final reduce: out[b] = (sum_dir0 + sum_dir1) / NP
// ---------------------------------------------------------------------------
__global__ void chamfer_final_kernel(float* __restrict__ out) {
    int b = threadIdx.x;
    if (b < BATCH) {
        float s = 0.0f;
        #pragma unroll
        for (int d = 0; d < 2; d++)
            #pragma unroll
            for (int i = 0; i < BLKX; i++)
                s += g_part[d][b][i];
        out[b] = s * (1.0f / (float)NP);
    }
}

extern "C" void kernel_launch(void* const* d_in, const int* in_sizes, int n_in,
                              void* d_out, int out_size) {
    const float* x1 = (const float*)d_in[0];
    const float* x2 = (const float*)d_in[1];
    float* out = (float*)d_out;

    int pre_threads = 2 * BATCH * (NP / 2);
    chamfer_pre_kernel<<<(pre_threads + 255) / 256, 256>>>(x1, x2);
    chamfer_min_kernel<<<dim3(BLKX, BATCH, 2), THREADS>>>(x1, x2);
    chamfer_final_kernel<<<1, 32>>>(out);
}